// round 7
// baseline (speedup 1.0000x reference)
#include <cuda_runtime.h>
#include <cuda_bf16.h>
#include <cstdint>

#define BB   256
#define II   512
#define RR   1024
#define UU   11
#define NOUT 4096
#define BK   32
#define LDB  80      // padded smem row stride in bytes (40 bf16)

// stage layout (bytes): Ahi 128*80, Alo 128*80, Whi 64*80, Wlo 64*80
#define AHI   0
#define ALO   10240
#define WHI   20480
#define WLO   25600
#define STAGE 30720
#define SMEM_TOTAL (2 * STAGE)   // 61440; epilogue gate buffer (128*68*4=34816) reuses it
#define GPITCH 68                // gate smem pitch in floats

// ---------------- double-buffered state (static; no allocation) ----------------
__device__ __align__(16) __nv_bfloat16 g_xhi[BB * II], g_xlo[BB * II];
__device__ __align__(16) __nv_bfloat16 g_h0hi[2][BB * RR], g_h0lo[2][BB * RR];
__device__ __align__(16) __nv_bfloat16 g_h1hi[2][BB * RR], g_h1lo[2][BB * RR];
__device__ __align__(16) float g_h1f[2][BB * RR];
__device__ __align__(16) float g_c0[2][BB * RR], g_c1[2][BB * RR];

static __device__ __forceinline__ uint32_t s2u(const void* p) {
    uint32_t a;
    asm("{ .reg .u64 t; cvta.to.shared.u64 t, %1; cvt.u32.u64 %0, t; }" : "=r"(a) : "l"(p));
    return a;
}
static __device__ __forceinline__ void cpa16(uint32_t s, const void* g) {
    asm volatile("cp.async.cg.shared.global [%0], [%1], 16;" :: "r"(s), "l"(g));
}
static __device__ __forceinline__ void ldsm4(uint32_t* r, uint32_t a) {
    asm volatile("ldmatrix.sync.aligned.m8n8.x4.shared.b16 {%0,%1,%2,%3}, [%4];"
                 : "=r"(r[0]), "=r"(r[1]), "=r"(r[2]), "=r"(r[3]) : "r"(a));
}
static __device__ __forceinline__ void mma16816(float* c, const uint32_t* a, const uint32_t* b) {
    asm volatile(
        "mma.sync.aligned.m16n8k16.row.col.f32.bf16.bf16.f32 "
        "{%0,%1,%2,%3}, {%4,%5,%6,%7}, {%8,%9}, {%0,%1,%2,%3};"
        : "+f"(c[0]), "+f"(c[1]), "+f"(c[2]), "+f"(c[3])
        : "r"(a[0]), "r"(a[1]), "r"(a[2]), "r"(a[3]), "r"(b[0]), "r"(b[1]));
}
static __device__ __forceinline__ float sigm(float x) { return 1.f / (1.f + __expf(-x)); }
static __device__ __forceinline__ void split_bf16(float v, __nv_bfloat16* hi, __nv_bfloat16* lo) {
    __nv_bfloat16 h = __float2bfloat16(v);
    *hi = h;
    *lo = __float2bfloat16(v - __bfloat162float(h));
}

// ======================= fused GEMM + LSTM cell =======================
// Grid (64, 2): x = n-tile (16 r-cols, gate-interleaved: W rows g*1024+x*16+j),
// y = m-half (128 batches). Each CTA: full K = K0 (op A0@W0) + K1 (op A1@W1),
// 3-pass bf16 hi/lo split with fp32 accum, then in-smem cell epilogue.
__global__ __launch_bounds__(256, 1) void step_k(
    const __nv_bfloat16* __restrict__ aHi0, const __nv_bfloat16* __restrict__ aLo0,
    int K0, const float* __restrict__ W0,
    const __nv_bfloat16* __restrict__ aHi1, const __nv_bfloat16* __restrict__ aLo1,
    int K1, const float* __restrict__ W1,
    const float* __restrict__ bi, const float* __restrict__ bh,
    const float* __restrict__ cIn, float* __restrict__ cOut,
    __nv_bfloat16* __restrict__ hHiOut, __nv_bfloat16* __restrict__ hLoOut,
    const float* __restrict__ h1In, float* __restrict__ h1Out,
    float* __restrict__ out, int u)
{
    extern __shared__ __align__(128) char sm[];
    const int tid = threadIdx.x, lane = tid & 31, wid = tid >> 5;
    const int wm = wid & 3, wn = wid >> 2;             // warps: 4(m) x 2(n)
    const uint32_t sb = s2u(sm);
    const int n16 = blockIdx.x * 16;
    const int mhalf = blockIdx.y;

    const int nch0 = K0 / BK;
    const int nch  = (K0 + K1) / BK;

    float acc[2][4][4];
#pragma unroll
    for (int i = 0; i < 2; i++)
#pragma unroll
        for (int j = 0; j < 4; j++)
#pragma unroll
            for (int q = 0; q < 4; q++) acc[i][j][q] = 0.f;

    // per-chunk source resolve (uniform)
#define RESOLVE(cc, AH, AL, WP, KK, KL)                                        \
    const __nv_bfloat16 *AH, *AL; const float* WP; int KK, KL;                 \
    if ((cc) < nch0) { AH = aHi0; AL = aLo0; WP = W0; KK = K0; KL = (cc) * BK; } \
    else             { AH = aHi1; AL = aLo1; WP = W1; KK = K1; KL = ((cc) - nch0) * BK; }

    // A cp.async: 128 rows x 32 bf16 per plane; thread -> (2 rows) x (16B seg)
    const int a_seg = tid & 3, a_rb = tid >> 2;
#define CPA(cc, stg) do {                                                      \
    RESOLVE(cc, _ah, _al, _wp, _K, _kl)                                        \
    const uint32_t _b = sb + (stg) * STAGE;                                    \
    _Pragma("unroll")                                                          \
    for (int p = 0; p < 2; p++) {                                              \
        const int r = p * 64 + a_rb;                                           \
        const size_t g = (size_t)(mhalf * 128 + r) * _K + _kl + a_seg * 8;     \
        const uint32_t so = r * LDB + a_seg * 16;                              \
        cpa16(_b + AHI + so, _ah + g);                                         \
        cpa16(_b + ALO + so, _al + g);                                         \
    }                                                                          \
    asm volatile("cp.async.commit_group;" ::: "memory");                       \
} while (0)

    // W LDG: 64 gate-interleaved rows x 32 fp32; thread -> 2 float4
    const int w_r = tid >> 3, w_f = tid & 7;          // rows 0..31 (+32), f 0..7... idx based
#define LDGW(cc, dst) do {                                                     \
    RESOLVE(cc, _ah, _al, _wp, _K, _kl)                                        \
    _Pragma("unroll")                                                          \
    for (int p = 0; p < 2; p++) {                                              \
        const int idx = p * 256 + tid, rr = idx >> 3, f = idx & 7;             \
        const int grow = (rr >> 4) * 1024 + n16 + (rr & 15);                   \
        (dst)[p] = *(const float4*)(_wp + (size_t)grow * _K + _kl + f * 4);    \
    }                                                                          \
} while (0)

#define STSW(src, stg) do {                                                    \
    char* _bp = sm + (stg) * STAGE;                                            \
    _Pragma("unroll")                                                          \
    for (int p = 0; p < 2; p++) {                                              \
        const int idx = p * 256 + tid, rr = idx >> 3, f = idx & 7;             \
        const float4 w = (src)[p];                                             \
        const __nv_bfloat16 h0 = __float2bfloat16(w.x), h1 = __float2bfloat16(w.y); \
        const __nv_bfloat16 h2 = __float2bfloat16(w.z), h3 = __float2bfloat16(w.w); \
        const __nv_bfloat16 l0 = __float2bfloat16(w.x - __bfloat162float(h0)); \
        const __nv_bfloat16 l1 = __float2bfloat16(w.y - __bfloat162float(h1)); \
        const __nv_bfloat16 l2 = __float2bfloat16(w.z - __bfloat162float(h2)); \
        const __nv_bfloat16 l3 = __float2bfloat16(w.w - __bfloat162float(h3)); \
        __nv_bfloat162 a01 = __halves2bfloat162(h0, h1), a23 = __halves2bfloat162(h2, h3); \
        __nv_bfloat162 b01 = __halves2bfloat162(l0, l1), b23 = __halves2bfloat162(l2, l3); \
        uint2 uh, ul;                                                          \
        uh.x = *(uint32_t*)&a01; uh.y = *(uint32_t*)&a23;                      \
        ul.x = *(uint32_t*)&b01; ul.y = *(uint32_t*)&b23;                      \
        *(uint2*)(_bp + WHI + rr * LDB + f * 8) = uh;                          \
        *(uint2*)(_bp + WLO + rr * LDB + f * 8) = ul;                          \
    }                                                                          \
} while (0)

    float4 wreg[2][2];

    // ---------- prologue ----------
    CPA(0, 0);
    LDGW(0, wreg[0]);
    LDGW(1, wreg[1]);
    CPA(1, 1);
    STSW(wreg[0], 0);
    asm volatile("cp.async.wait_group 1;" ::: "memory");
    __syncthreads();

    // ---------- main loop: one sync per chunk ----------
    for (int c = 0; c < nch; c++) {
        const int p = c & 1;
        const uint32_t base = sb + p * STAGE;

        // compute chunk c
#pragma unroll
        for (int kk = 0; kk < 2; kk++) {
            const int ar = (lane & 7) + ((lane >> 3) & 1) * 8;
            const int ac = kk * 16 + (lane >> 4) * 8;
            uint32_t ah[2][4], al[2][4];
#pragma unroll
            for (int i = 0; i < 2; i++) {
                const int row = wm * 32 + i * 16 + ar;
                ldsm4(ah[i], base + AHI + row * LDB + ac * 2);
                ldsm4(al[i], base + ALO + row * LDB + ac * 2);
            }
            const int br = (lane & 7) + (lane >> 4) * 8;
            const int bc = kk * 16 + ((lane >> 3) & 1) * 8;
            uint32_t wh[8], wl[8];
#pragma unroll
            for (int j2 = 0; j2 < 2; j2++) {
                const int row = wn * 32 + j2 * 16 + br;
                ldsm4(wh + j2 * 4, base + WHI + row * LDB + bc * 2);
                ldsm4(wl + j2 * 4, base + WLO + row * LDB + bc * 2);
            }
#pragma unroll
            for (int i = 0; i < 2; i++)
#pragma unroll
                for (int j = 0; j < 4; j++) {
                    const uint32_t* bh2 = &wh[(j >> 1) * 4 + (j & 1) * 2];
                    const uint32_t* bl2 = &wl[(j >> 1) * 4 + (j & 1) * 2];
                    mma16816(acc[i][j], ah[i], bh2);
                    mma16816(acc[i][j], ah[i], bl2);
                    mma16816(acc[i][j], al[i], bh2);
                }
        }

        if (c + 1 < nch) STSW(wreg[(c + 1) & 1], 1 - p);   // stage 1-p: old readers synced
        if (c + 2 < nch) LDGW(c + 2, wreg[c & 1]);
        asm volatile("cp.async.wait_group 0;" ::: "memory"); // A(c+1) landed
        __syncthreads();
        if (c + 2 < nch) CPA(c + 2, p);                      // stage p: readers done
    }

    // ---------- epilogue: gates -> smem -> LSTM cell ----------
    float* sg = (float*)sm;     // [128][GPITCH]
#pragma unroll
    for (int i = 0; i < 2; i++) {
        const int row = wm * 32 + i * 16 + (lane >> 2);
#pragma unroll
        for (int j = 0; j < 4; j++) {
            const int col = wn * 32 + j * 8 + (lane & 3) * 2;
            *(float2*)&sg[row * GPITCH + col]       = *(float2*)&acc[i][j][0];
            *(float2*)&sg[(row + 8) * GPITCH + col] = *(float2*)&acc[i][j][2];
        }
    }
    __syncthreads();

    {
        const int m = tid >> 1;
        const int b = mhalf * 128 + m;
#pragma unroll
        for (int q = 0; q < 8; q++) {
            const int j = (tid & 1) * 8 + q;
            const int rg = n16 + j;
            const int idx = b * RR + rg;
            const int ni = 0 * 1024 + rg, nf = 1 * 1024 + rg,
                      no = 2 * 1024 + rg, ng = 3 * 1024 + rg;
            float gi = sg[m * GPITCH + j]      + bi[ni] + bh[ni];
            float gf = sg[m * GPITCH + 16 + j] + bi[nf] + bh[nf];
            float go = sg[m * GPITCH + 32 + j] + bi[no] + bh[no];
            float gg = sg[m * GPITCH + 48 + j] + bi[ng] + bh[ng];
            if (out) out[(size_t)b * (UU * RR) + (size_t)u * RR + rg] = h1In[idx];
            float c = sigm(gf) * cIn[idx] + sigm(gi) * tanhf(gg);
            cOut[idx] = c;
            float h = sigm(go) * tanhf(c);
            if (h1Out) h1Out[idx] = h;
            split_bf16(h, &hHiOut[idx], &hLoOut[idx]);
        }
    }
}

// ---------------- init kernels ----------------
__global__ void convert_x_k(const float* __restrict__ x) {
    int idx = blockIdx.x * blockDim.x + threadIdx.x;
    if (idx >= BB * II) return;
    split_bf16(x[idx], &g_xhi[idx], &g_xlo[idx]);
}
__global__ void init_states_k(const float* __restrict__ st) {
    int idx = blockIdx.x * blockDim.x + threadIdx.x;
    if (idx >= BB * RR) return;
    int b = idx >> 10, r = idx & 1023;
    const float* p = st + (size_t)b * 4 * RR + r;
    split_bf16(p[0 * RR], &g_h0hi[0][idx], &g_h0lo[0][idx]);
    g_c0[0][idx] = p[1 * RR];
    float h1 = p[2 * RR];
    g_h1f[0][idx] = h1;
    split_bf16(h1, &g_h1hi[0][idx], &g_h1lo[0][idx]);
    g_c1[0][idx] = p[3 * RR];
}

// ---------------- launch ----------------
extern "C" void kernel_launch(void* const* d_in, const int* in_sizes, int n_in,
                              void* d_out, int out_size) {
    const float* x   = (const float*)d_in[0];
    const float* st  = (const float*)d_in[1];
    const float* Wi0 = (const float*)d_in[2];
    const float* bi0 = (const float*)d_in[3];
    const float* Wh0 = (const float*)d_in[4];
    const float* bh0 = (const float*)d_in[5];
    const float* Wi1 = (const float*)d_in[6];
    const float* bi1 = (const float*)d_in[7];
    const float* Wh1 = (const float*)d_in[8];
    const float* bh1 = (const float*)d_in[9];
    float* out = (float*)d_out;

    cudaFuncSetAttribute(step_k, cudaFuncAttributeMaxDynamicSharedMemorySize, SMEM_TOTAL);

    void* p;
    __nv_bfloat16 *xhi, *xlo, *h0hi[2], *h0lo[2], *h1hi[2], *h1lo[2];
    float *c0[2], *c1[2], *h1f[2];
    cudaGetSymbolAddress(&p, g_xhi);  xhi = (__nv_bfloat16*)p;
    cudaGetSymbolAddress(&p, g_xlo);  xlo = (__nv_bfloat16*)p;
    cudaGetSymbolAddress(&p, g_h0hi); h0hi[0] = (__nv_bfloat16*)p; h0hi[1] = h0hi[0] + BB * RR;
    cudaGetSymbolAddress(&p, g_h0lo); h0lo[0] = (__nv_bfloat16*)p; h0lo[1] = h0lo[0] + BB * RR;
    cudaGetSymbolAddress(&p, g_h1hi); h1hi[0] = (__nv_bfloat16*)p; h1hi[1] = h1hi[0] + BB * RR;
    cudaGetSymbolAddress(&p, g_h1lo); h1lo[0] = (__nv_bfloat16*)p; h1lo[1] = h1lo[0] + BB * RR;
    cudaGetSymbolAddress(&p, g_c0);   c0[0] = (float*)p; c0[1] = c0[0] + BB * RR;
    cudaGetSymbolAddress(&p, g_c1);   c1[0] = (float*)p; c1[1] = c1[0] + BB * RR;
    cudaGetSymbolAddress(&p, g_h1f);  h1f[0] = (float*)p; h1f[1] = h1f[0] + BB * RR;

    convert_x_k<<<(BB * II + 255) / 256, 256>>>(x);
    init_states_k<<<(BB * RR + 255) / 256, 256>>>(st);

    const dim3 gg(NOUT / 64, 2);   // 64 n-tiles x 2 m-halves = 128 CTAs

    for (int u = 0; u < UU; u++) {
        const int ru = u & 1, wu = ru ^ 1;
        // layer 0: pre0 = x@Wi0[u]^T + h0@Wh0[u]^T (+biases) -> cell0 -> h0[wu], c0[wu]
        step_k<<<gg, 256, SMEM_TOTAL>>>(
            xhi, xlo, II, Wi0 + (size_t)u * NOUT * II,
            h0hi[ru], h0lo[ru], RR, Wh0 + (size_t)u * NOUT * RR,
            bi0 + (size_t)u * NOUT, bh0 + (size_t)u * NOUT,
            c0[ru], c0[wu], h0hi[wu], h0lo[wu],
            nullptr, nullptr, nullptr, u);
        // layer 1: pre1 = h0_new@Wi1[u]^T + h1@Wh1[u]^T -> out(h1_old), cell1 -> h1[wu], c1[wu]
        step_k<<<gg, 256, SMEM_TOTAL>>>(
            h0hi[wu], h0lo[wu], RR, Wi1 + (size_t)u * NOUT * RR,
            h1hi[ru], h1lo[ru], RR, Wh1 + (size_t)u * NOUT * RR,
            bi1 + (size_t)u * NOUT, bh1 + (size_t)u * NOUT,
            c1[ru], c1[wu], h1hi[wu], h1lo[wu],
            h1f[ru], h1f[wu], out, u);
    }
}

// round 9
// speedup vs baseline: 1.7385x; 1.7385x over previous
#include <cuda_runtime.h>
#include <cuda_bf16.h>
#include <cstdint>

#define BB   256
#define II   512
#define RR   1024
#define UU   11
#define NOUT 4096
#define BN   64
#define BK   32
#define LDB  80      // padded smem row stride in bytes (40 bf16)

// stage layout (bytes): Ahi 256*80, Alo 256*80, Whi 64*80, Wlo 64*80
#define AHI   0
#define ALO   20480
#define WHI   40960
#define WLO   46080
#define STAGE 51200
#define SMEM_TOTAL (2 * STAGE)   // 102400

// ---------------- scratch (static; no allocation) ----------------
__device__ __align__(16) float g_pre0[2 * BB * NOUT];   // two K-half partials
__device__ __align__(16) float g_pre1[2 * BB * NOUT];
__device__ __align__(16) __nv_bfloat16 g_xhi[BB * II], g_xlo[BB * II];
__device__ __align__(16) __nv_bfloat16 g_h0hi[BB * RR], g_h0lo[BB * RR];
__device__ __align__(16) __nv_bfloat16 g_h1hi[BB * RR], g_h1lo[BB * RR];
__device__ __align__(16) float g_h1[BB * RR];
__device__ __align__(16) float g_c0[BB * RR], g_c1[BB * RR];

static __device__ __forceinline__ uint32_t s2u(const void* p) {
    uint32_t a;
    asm("{ .reg .u64 t; cvta.to.shared.u64 t, %1; cvt.u32.u64 %0, t; }" : "=r"(a) : "l"(p));
    return a;
}
static __device__ __forceinline__ void cpa16(uint32_t s, const void* g) {
    asm volatile("cp.async.cg.shared.global [%0], [%1], 16;" :: "r"(s), "l"(g));
}
static __device__ __forceinline__ void ldsm4(uint32_t* r, uint32_t a) {
    asm volatile("ldmatrix.sync.aligned.m8n8.x4.shared.b16 {%0,%1,%2,%3}, [%4];"
                 : "=r"(r[0]), "=r"(r[1]), "=r"(r[2]), "=r"(r[3]) : "r"(a));
}
static __device__ __forceinline__ void mma16816(float* c, const uint32_t* a, const uint32_t* b) {
    asm volatile(
        "mma.sync.aligned.m16n8k16.row.col.f32.bf16.bf16.f32 "
        "{%0,%1,%2,%3}, {%4,%5,%6,%7}, {%8,%9}, {%0,%1,%2,%3};"
        : "+f"(c[0]), "+f"(c[1]), "+f"(c[2]), "+f"(c[3])
        : "r"(a[0]), "r"(a[1]), "r"(a[2]), "r"(a[3]), "r"(b[0]), "r"(b[1]));
}
// pack hi-16 bits of two fp32 into one bf16x2 reg (truncation; lo plane is exact remainder)
static __device__ __forceinline__ uint32_t prmt_hi(uint32_t x, uint32_t y) {
    uint32_t r;
    asm("prmt.b32 %0, %1, %2, 0x7632;" : "=r"(r) : "r"(x), "r"(y));
    return r;
}
static __device__ __forceinline__ uint32_t cvt_bf2(float x, float y) {
    uint32_t r;
    asm("cvt.rn.bf16x2.f32 %0, %1, %2;" : "=r"(r) : "f"(y), "f"(x));
    return r;
}
// split float4 -> hi/lo bf16x2 planes and store into stage smem
static __device__ __forceinline__ void stsw(float4 v, char* bp, int wr, int wf) {
    const uint32_t ux = __float_as_uint(v.x), uy = __float_as_uint(v.y);
    const uint32_t uz = __float_as_uint(v.z), uw = __float_as_uint(v.w);
    uint2 uh, ul;
    uh.x = prmt_hi(ux, uy);
    uh.y = prmt_hi(uz, uw);
    ul.x = cvt_bf2(v.x - __uint_as_float(ux & 0xFFFF0000u),
                   v.y - __uint_as_float(uy & 0xFFFF0000u));
    ul.y = cvt_bf2(v.z - __uint_as_float(uz & 0xFFFF0000u),
                   v.w - __uint_as_float(uw & 0xFFFF0000u));
    *(uint2*)(bp + WHI + wr * LDB + wf * 8) = uh;
    *(uint2*)(bp + WLO + wr * LDB + wf * 8) = ul;
}

// ---------------- 3-pass bf16 HMMA partial GEMM ----------------
// C_part[half] (256 x 4096) = partial over one half of concatenated K:
//   [A0 (256 x K0)] @ [W0 (4096 x K0)]^T  ++  [A1 (256 x K1)] @ [W1 (4096 x K1)]^T
// A as bf16 hi/lo planes; W fp32 split on the fly.
__global__ __launch_bounds__(512, 1) void gemm_tc(
    const __nv_bfloat16* __restrict__ a0hi, const __nv_bfloat16* __restrict__ a0lo,
    int K0, const float* __restrict__ W0,
    const __nv_bfloat16* __restrict__ a1hi, const __nv_bfloat16* __restrict__ a1lo,
    int K1, const float* __restrict__ W1,
    float* __restrict__ C)
{
    extern __shared__ __align__(128) char sm[];
    const int tid = threadIdx.x, lane = tid & 31, wid = tid >> 5;
    const int wm = wid & 3, wn = wid >> 2;         // warps: 4(m) x 4(n)
    const uint32_t sb = s2u(sm);

    const int n0 = blockIdx.x * BN;
    const int nch = (K0 + K1) / (2 * BK);          // chunks in this K-half
    const int cbase = blockIdx.y * nch;            // global chunk offset
    const int nch0 = K0 / BK;
    C += (size_t)blockIdx.y * BB * NOUT;

    float acc[4][2][4];
#pragma unroll
    for (int i = 0; i < 4; i++)
#pragma unroll
        for (int j = 0; j < 2; j++)
#pragma unroll
            for (int q = 0; q < 4; q++) acc[i][j][q] = 0.f;

#define RESOLVE(cc, AH, AL, WP, KK, KL)                                          \
    const __nv_bfloat16 *AH, *AL; const float* WP; int KK, KL;                   \
    { const int _g = cbase + (cc);                                               \
      if (_g < nch0) { AH = a0hi; AL = a0lo; WP = W0; KK = K0; KL = _g * BK; }   \
      else           { AH = a1hi; AL = a1lo; WP = W1; KK = K1; KL = (_g - nch0) * BK; } }

    // A cp.async: 256 rows x 32 bf16 x 2 planes; 512 thr -> (2 rows each) x 16B seg
    const int a_seg = tid & 3, a_rb = tid >> 2;
#define CPA(cc, stg) do {                                                        \
    RESOLVE(cc, _ah, _al, _wp, _K, _kl)                                          \
    const uint32_t _b = sb + (stg) * STAGE;                                      \
    _Pragma("unroll")                                                            \
    for (int p = 0; p < 2; p++) {                                                \
        const int r = p * 128 + a_rb;                                            \
        const size_t g = (size_t)r * _K + _kl + a_seg * 8;                       \
        const uint32_t so = r * LDB + a_seg * 16;                                \
        cpa16(_b + AHI + so, _ah + g);                                           \
        cpa16(_b + ALO + so, _al + g);                                           \
    }                                                                            \
    asm volatile("cp.async.commit_group;" ::: "memory");                         \
} while (0)

    // W LDG: 64 rows x 32 fp32 = 512 float4, one per thread
    const int w_r = tid >> 3, w_f = tid & 7;
#define LDGW(cc, dst) do {                                                       \
    RESOLVE(cc, _ah, _al, _wp, _K, _kl)                                          \
    (dst) = *(const float4*)(_wp + (size_t)(n0 + w_r) * _K + _kl + w_f * 4);     \
} while (0)

    float4 wreg;

    // ---------- prologue ----------
    CPA(0, 0);
    LDGW(0, wreg);

    // ---------- main loop (R4-proven 2-sync structure) ----------
    for (int c = 0; c < nch; c++) {
        const int p = c & 1;
        const uint32_t base = sb + p * STAGE;

        stsw(wreg, sm + p * STAGE, w_r, w_f);   // W(c) into stage p
        if (c + 1 < nch) {
            CPA(c + 1, 1 - p);
            asm volatile("cp.async.wait_group 1;" ::: "memory");   // A(c) landed
        } else {
            asm volatile("cp.async.wait_group 0;" ::: "memory");
        }
        __syncthreads();

        // compute chunk c
#pragma unroll
        for (int kk = 0; kk < 2; kk++) {
            const int ar = (lane & 7) + ((lane >> 3) & 1) * 8;
            const int ac = kk * 16 + (lane >> 4) * 8;
            uint32_t ah[4][4], al[4][4];
#pragma unroll
            for (int i = 0; i < 4; i++) {
                const int row = wm * 64 + i * 16 + ar;
                ldsm4(ah[i], base + AHI + row * LDB + ac * 2);
                ldsm4(al[i], base + ALO + row * LDB + ac * 2);
            }
            const int br = (lane & 7) + (lane >> 4) * 8;
            const int bc = kk * 16 + ((lane >> 3) & 1) * 8;
            uint32_t wh[4], wl[4];
            {
                const int row = wn * 16 + br;
                ldsm4(wh, base + WHI + row * LDB + bc * 2);
                ldsm4(wl, base + WLO + row * LDB + bc * 2);
            }
#pragma unroll
            for (int i = 0; i < 4; i++)
#pragma unroll
                for (int j = 0; j < 2; j++) {
                    const uint32_t* bh2 = &wh[j * 2];
                    const uint32_t* bl2 = &wl[j * 2];
                    mma16816(acc[i][j], ah[i], bh2);
                    mma16816(acc[i][j], ah[i], bl2);
                    mma16816(acc[i][j], al[i], bh2);
                }
        }

        if (c + 1 < nch) LDGW(c + 1, wreg);  // prefetch W(c+1) into regs
        __syncthreads();
    }

    // ---------- epilogue ----------
#pragma unroll
    for (int i = 0; i < 4; i++) {
        const int m = wm * 64 + i * 16 + (lane >> 2);
#pragma unroll
        for (int j = 0; j < 2; j++) {
            const int col = n0 + wn * 16 + j * 8 + (lane & 3) * 2;
            *(float2*)&C[(size_t)m * NOUT + col]       = *(float2*)&acc[i][j][0];
            *(float2*)&C[(size_t)(m + 8) * NOUT + col] = *(float2*)&acc[i][j][2];
        }
    }
}

// ---------------- elementwise kernels ----------------
static __device__ __forceinline__ float sigm(float x) { return 1.f / (1.f + __expf(-x)); }
static __device__ __forceinline__ void split_bf16(float v, __nv_bfloat16* hi, __nv_bfloat16* lo) {
    __nv_bfloat16 h = __float2bfloat16(v);
    *hi = h;
    *lo = __float2bfloat16(v - __bfloat162float(h));
}

__global__ void convert_x_k(const float* __restrict__ x) {
    int idx = blockIdx.x * blockDim.x + threadIdx.x;
    if (idx >= BB * II) return;
    split_bf16(x[idx], &g_xhi[idx], &g_xlo[idx]);
}

__global__ void init_states_k(const float* __restrict__ st) {
    int idx = blockIdx.x * blockDim.x + threadIdx.x;
    if (idx >= BB * RR) return;
    int b = idx >> 10, r = idx & 1023;
    const float* p = st + (size_t)b * 4 * RR + r;
    split_bf16(p[0 * RR], &g_h0hi[idx], &g_h0lo[idx]);
    g_c0[idx] = p[1 * RR];
    float h1 = p[2 * RR];
    g_h1[idx] = h1;
    split_bf16(h1, &g_h1hi[idx], &g_h1lo[idx]);
    g_c1[idx] = p[3 * RR];
}

__global__ void cell0_k(const float* __restrict__ bi, const float* __restrict__ bh) {
    int idx = blockIdx.x * blockDim.x + threadIdx.x;
    int b = idx >> 10, r = idx & 1023;
    const float* p0 = g_pre0 + (size_t)b * NOUT;
    const float* p1 = g_pre0 + (size_t)BB * NOUT + (size_t)b * NOUT;
    float gi = p0[r]          + p1[r]          + bi[r]          + bh[r];
    float gf = p0[RR + r]     + p1[RR + r]     + bi[RR + r]     + bh[RR + r];
    float go = p0[2 * RR + r] + p1[2 * RR + r] + bi[2 * RR + r] + bh[2 * RR + r];
    float gg = p0[3 * RR + r] + p1[3 * RR + r] + bi[3 * RR + r] + bh[3 * RR + r];
    float c = sigm(gf) * g_c0[idx] + sigm(gi) * tanhf(gg);
    g_c0[idx] = c;
    float h = sigm(go) * tanhf(c);
    split_bf16(h, &g_h0hi[idx], &g_h0lo[idx]);
}

__global__ void cell1_k(const float* __restrict__ bi, const float* __restrict__ bh,
                        float* __restrict__ out, int u) {
    int idx = blockIdx.x * blockDim.x + threadIdx.x;
    int b = idx >> 10, r = idx & 1023;
    // ys[u] = h1 BEFORE this step's update
    out[(size_t)b * (UU * RR) + (size_t)u * RR + r] = g_h1[idx];
    const float* p0 = g_pre1 + (size_t)b * NOUT;
    const float* p1 = g_pre1 + (size_t)BB * NOUT + (size_t)b * NOUT;
    float gi = p0[r]          + p1[r]          + bi[r]          + bh[r];
    float gf = p0[RR + r]     + p1[RR + r]     + bi[RR + r]     + bh[RR + r];
    float go = p0[2 * RR + r] + p1[2 * RR + r] + bi[2 * RR + r] + bh[2 * RR + r];
    float gg = p0[3 * RR + r] + p1[3 * RR + r] + bi[3 * RR + r] + bh[3 * RR + r];
    float c = sigm(gf) * g_c1[idx] + sigm(gi) * tanhf(gg);
    g_c1[idx] = c;
    float h = sigm(go) * tanhf(c);
    g_h1[idx] = h;
    split_bf16(h, &g_h1hi[idx], &g_h1lo[idx]);
}

// ---------------- launch ----------------
extern "C" void kernel_launch(void* const* d_in, const int* in_sizes, int n_in,
                              void* d_out, int out_size) {
    const float* x   = (const float*)d_in[0];
    const float* st  = (const float*)d_in[1];
    const float* Wi0 = (const float*)d_in[2];
    const float* bi0 = (const float*)d_in[3];
    const float* Wh0 = (const float*)d_in[4];
    const float* bh0 = (const float*)d_in[5];
    const float* Wi1 = (const float*)d_in[6];
    const float* bi1 = (const float*)d_in[7];
    const float* Wh1 = (const float*)d_in[8];
    const float* bh1 = (const float*)d_in[9];
    float* out = (float*)d_out;

    cudaFuncSetAttribute(gemm_tc, cudaFuncAttributeMaxDynamicSharedMemorySize, SMEM_TOTAL);

    void* p;
    float *pre0, *pre1;
    __nv_bfloat16 *xhi, *xlo, *h0hi, *h0lo, *h1hi, *h1lo;
    cudaGetSymbolAddress(&p, g_pre0); pre0 = (float*)p;
    cudaGetSymbolAddress(&p, g_pre1); pre1 = (float*)p;
    cudaGetSymbolAddress(&p, g_xhi);  xhi  = (__nv_bfloat16*)p;
    cudaGetSymbolAddress(&p, g_xlo);  xlo  = (__nv_bfloat16*)p;
    cudaGetSymbolAddress(&p, g_h0hi); h0hi = (__nv_bfloat16*)p;
    cudaGetSymbolAddress(&p, g_h0lo); h0lo = (__nv_bfloat16*)p;
    cudaGetSymbolAddress(&p, g_h1hi); h1hi = (__nv_bfloat16*)p;
    cudaGetSymbolAddress(&p, g_h1lo); h1lo = (__nv_bfloat16*)p;

    convert_x_k<<<(BB * II + 255) / 256, 256>>>(x);
    init_states_k<<<(BB * RR + 255) / 256, 256>>>(st);

    const dim3 gg(NOUT / BN, 2);        // 64 n-tiles x 2 K-halves
    const int cell_blocks = (BB * RR) / 256;

    for (int u = 0; u < UU; u++) {
        gemm_tc<<<gg, 512, SMEM_TOTAL>>>(
            xhi,  xlo,  II, Wi0 + (size_t)u * NOUT * II,
            h0hi, h0lo, RR, Wh0 + (size_t)u * NOUT * RR,
            pre0);
        cell0_k<<<cell_blocks, 256>>>(bi0 + (size_t)u * NOUT, bh0 + (size_t)u * NOUT);

        gemm_tc<<<gg, 512, SMEM_TOTAL>>>(
            h0hi, h0lo, RR, Wi1 + (size_t)u * NOUT * RR,
            h1hi, h1lo, RR, Wh1 + (size_t)u * NOUT * RR,
            pre1);
        cell1_k<<<cell_blocks, 256>>>(bi1 + (size_t)u * NOUT, bh1 + (size_t)u * NOUT, out, u);
    }
}